// round 15
// baseline (speedup 1.0000x reference)
#include <cuda_runtime.h>
#include <cstdint>
#include <math.h>

#define NB 64
#define LOOKBACK 32
#define NS 256
#define DM 512
#define DK 128
#define DV 128
#define WPC 4                   // warps per CTA in main
#define WST 2                   // stocks per warp (single burst)
#define SPC (WPC * WST)         // 8 stocks per CTA
#define CPB (NS / SPC)          // 32 CTAs per batch
#define NPART CPB               // 32 CTA-partials per batch

// ---- scratch (device globals: allocation-free) ----
__device__ float  g_upart[NB * 4 * DM];     // 4 partial u slices per batch
__device__ float4 g_stock[NS];              // {alpha, gate, lag_floor, lag_ceil}
__device__ float  g_pctx[NB * NPART * DM];  // CTA partial contexts (unnormalized)
__device__ float  g_l[NB * NPART];          // CTA partial exp-sums
__device__ unsigned int g_cnt[NB];          // arrival counters (zeroed in prep)

__device__ __forceinline__ float sigmoidf_(float x) {
    return 1.0f / (1.0f + __expf(-x));
}

// ============================================================================
// Kernel 1: prep. grid (4, NB) x 256 threads. CTA (g, b) computes
// q[b, g*32 .. g*32+32) and the partial u from those 32 k's into g_upart.
// ============================================================================
__global__ __launch_bounds__(256) void prep_kernel(
    const float* __restrict__ query,
    const float* __restrict__ Wq,
    const float* __restrict__ Wk,
    const float* __restrict__ lags,
    const float* __restrict__ gates,
    const void*  __restrict__ mlraw)
{
    __shared__ float  qs[DM];
    __shared__ float  qks[32];
    __shared__ float4 sred[2][DM / 4];

    const int tid = threadIdx.x;    // 0..255
    const int g   = blockIdx.x;     // 0..3 k-slice
    const int b   = blockIdx.y;     // batch

    if (g == 0 && tid == 0) g_cnt[b] = 0u;

    // per-stock meta (one CTA)
    if (g == 0 && b == 0) {
        float ml = 16.0f;
        if (mlraw != nullptr) {
            int   iv = ((const int*)mlraw)[0];
            float fv = ((const float*)mlraw)[0];
            ml = (iv > 0 && iv <= 65536) ? (float)iv : fv;
        }
        float lag = sigmoidf_(lags[tid]) * ml;
        int ifl = min(max((int)floorf(lag), 0), LOOKBACK - 1);
        int icl = min(max((int)ceilf(lag),  0), LOOKBACK - 1);
        float alpha = lag - (float)ifl;
        float gate  = sigmoidf_(gates[tid]);
        g_stock[tid] = make_float4(alpha, gate, (float)ifl, (float)icl);
    }

    qs[tid]       = query[(size_t)b * DM + tid];
    qs[tid + 256] = query[(size_t)b * DM + tid + 256];
    __syncthreads();

    // ---- stage A: q[k] for this CTA's 32-slice (warp-per-k, 4 rounds) ----
    const int wid  = tid >> 5;     // 0..7
    const int lane = tid & 31;
    #pragma unroll
    for (int r = 0; r < 4; r++) {
        const int kl = r * 8 + wid;
        const int k  = g * 32 + kl;
        float acc = 0.f;
        #pragma unroll
        for (int i = 0; i < 16; i++)
            acc = fmaf(Wq[(size_t)k * DM + i * 32 + lane], qs[i * 32 + lane], acc);
        #pragma unroll
        for (int off = 16; off; off >>= 1)
            acc += __shfl_xor_sync(0xffffffffu, acc, off);
        if (lane == 0) qks[kl] = acc;
    }
    __syncthreads();

    // ---- stage B: partial u over this CTA's 32 k's, K split 2 ways ----
    const int col  = tid & 127;    // float4 column
    const int half = tid >> 7;     // 0..1
    float4 acc = make_float4(0.f, 0.f, 0.f, 0.f);
    const float4* wkb = (const float4*)Wk + (size_t)(g * 32 + half * 16) * (DM / 4) + col;
    #pragma unroll
    for (int kk = 0; kk < 16; kk++) {
        const float  s = qks[half * 16 + kk];
        const float4 w = wkb[(size_t)kk * (DM / 4)];
        acc.x = fmaf(s, w.x, acc.x); acc.y = fmaf(s, w.y, acc.y);
        acc.z = fmaf(s, w.z, acc.z); acc.w = fmaf(s, w.w, acc.w);
    }
    sred[half][col] = acc;
    __syncthreads();

    if (tid < 128) {
        const float inv = 0.08838834764831845f;  // 1/sqrt(128)
        const float4 a = sred[0][tid], c = sred[1][tid];
        float4 r;
        r.x = (a.x + c.x) * inv; r.y = (a.y + c.y) * inv;
        r.z = (a.z + c.z) * inv; r.w = (a.w + c.w) * inv;
        ((float4*)g_upart)[((size_t)b * 4 + g) * (DM / 4) + tid] = r;
    }
}

// ============================================================================
// Kernel 2: main. ONE load burst per warp: 2 stocks (16 LDG.128, 64 payload
// regs) fully register-resident through the single pass. No re-read, no-max
// softmax, plain-sum combines. 128 thr / 4 warps, <=255 regs (launch_bounds
// (128,2)), grid (CPB=32, NB) = 2048 CTAs -> 7 short waves. Fused finish.
// ============================================================================
__global__ __launch_bounds__(128, 2) void main_kernel(
    const float* __restrict__ embs,
    const float* __restrict__ Wv,
    float*       __restrict__ out)
{
    __shared__ float4 sctx[WPC * (DM / 4)];   // 8 KB combine scratch
    __shared__ float  sl[WPC];
    __shared__ unsigned int slast;

    const int tid  = threadIdx.x;
    const int lane = tid & 31;
    const int wid  = tid >> 5;        // 0..3
    const int b    = blockIdx.y;
    const int sp   = blockIdx.x;
    const int s0   = (sp * WPC + wid) * WST;

    const float4* __restrict__ base =
        (const float4*)embs + (size_t)b * LOOKBACK * NS * (DM / 4);

    // hoisted meta + row offsets
    const float4 mtA = g_stock[s0];
    const float4 mtB = g_stock[s0 + 1];
    const int rfa = ((int)mtA.z * NS + s0) * (DM / 4);
    const int rca = ((int)mtA.w * NS + s0) * (DM / 4);
    const int rfb = ((int)mtB.z * NS + s0 + 1) * (DM / 4);
    const int rcb = ((int)mtB.w * NS + s0 + 1) * (DM / 4);

    // u[b] = sum of 4 partial slices (16 regs)
    const float4* up = (const float4*)g_upart + (size_t)b * 4 * (DM / 4);
    float4 u0, u1, u2, u3;
    {
        float4 t0 = up[lane],       t1 = up[128 + lane];
        float4 t2 = up[256 + lane], t3 = up[384 + lane];
        u0 = make_float4(t0.x+t1.x+t2.x+t3.x, t0.y+t1.y+t2.y+t3.y,
                         t0.z+t1.z+t2.z+t3.z, t0.w+t1.w+t2.w+t3.w);
        t0 = up[32+lane]; t1 = up[160+lane]; t2 = up[288+lane]; t3 = up[416+lane];
        u1 = make_float4(t0.x+t1.x+t2.x+t3.x, t0.y+t1.y+t2.y+t3.y,
                         t0.z+t1.z+t2.z+t3.z, t0.w+t1.w+t2.w+t3.w);
        t0 = up[64+lane]; t1 = up[192+lane]; t2 = up[320+lane]; t3 = up[448+lane];
        u2 = make_float4(t0.x+t1.x+t2.x+t3.x, t0.y+t1.y+t2.y+t3.y,
                         t0.z+t1.z+t2.z+t3.z, t0.w+t1.w+t2.w+t3.w);
        t0 = up[96+lane]; t1 = up[224+lane]; t2 = up[352+lane]; t3 = up[480+lane];
        u3 = make_float4(t0.x+t1.x+t2.x+t3.x, t0.y+t1.y+t2.y+t3.y,
                         t0.z+t1.z+t2.z+t3.z, t0.w+t1.w+t2.w+t3.w);
    }

    // ---- THE burst: all 16 LDG.128 of both stocks, front-batched ----
    float4 fa0 = base[rfa + lane],      fa1 = base[rfa + 32 + lane];
    float4 fa2 = base[rfa + 64 + lane], fa3 = base[rfa + 96 + lane];
    float4 ca0 = base[rca + lane],      ca1 = base[rca + 32 + lane];
    float4 ca2 = base[rca + 64 + lane], ca3 = base[rca + 96 + lane];
    float4 fb0 = base[rfb + lane],      fb1 = base[rfb + 32 + lane];
    float4 fb2 = base[rfb + 64 + lane], fb3 = base[rfb + 96 + lane];
    float4 cb0 = base[rcb + lane],      cb1 = base[rcb + 32 + lane];
    float4 cb2 = base[rcb + 64 + lane], cb3 = base[rcb + 96 + lane];

    // interpolate in place: f <- (1-a)f + a c  (e stays in registers)
    {
        const float a = mtA.x, oma = 1.0f - a;
        fa0.x = oma*fa0.x + a*ca0.x; fa0.y = oma*fa0.y + a*ca0.y; fa0.z = oma*fa0.z + a*ca0.z; fa0.w = oma*fa0.w + a*ca0.w;
        fa1.x = oma*fa1.x + a*ca1.x; fa1.y = oma*fa1.y + a*ca1.y; fa1.z = oma*fa1.z + a*ca1.z; fa1.w = oma*fa1.w + a*ca1.w;
        fa2.x = oma*fa2.x + a*ca2.x; fa2.y = oma*fa2.y + a*ca2.y; fa2.z = oma*fa2.z + a*ca2.z; fa2.w = oma*fa2.w + a*ca2.w;
        fa3.x = oma*fa3.x + a*ca3.x; fa3.y = oma*fa3.y + a*ca3.y; fa3.z = oma*fa3.z + a*ca3.z; fa3.w = oma*fa3.w + a*ca3.w;
    }
    {
        const float a = mtB.x, oma = 1.0f - a;
        fb0.x = oma*fb0.x + a*cb0.x; fb0.y = oma*fb0.y + a*cb0.y; fb0.z = oma*fb0.z + a*cb0.z; fb0.w = oma*fb0.w + a*cb0.w;
        fb1.x = oma*fb1.x + a*cb1.x; fb1.y = oma*fb1.y + a*cb1.y; fb1.z = oma*fb1.z + a*cb1.z; fb1.w = oma*fb1.w + a*cb1.w;
        fb2.x = oma*fb2.x + a*cb2.x; fb2.y = oma*fb2.y + a*cb2.y; fb2.z = oma*fb2.z + a*cb2.z; fb2.w = oma*fb2.w + a*cb2.w;
        fb3.x = oma*fb3.x + a*cb3.x; fb3.y = oma*fb3.y + a*cb3.y; fb3.z = oma*fb3.z + a*cb3.z; fb3.w = oma*fb3.w + a*cb3.w;
    }

    // dots
    float pA = fa0.x*u0.x + fa0.y*u0.y + fa0.z*u0.z + fa0.w*u0.w
             + fa1.x*u1.x + fa1.y*u1.y + fa1.z*u1.z + fa1.w*u1.w
             + fa2.x*u2.x + fa2.y*u2.y + fa2.z*u2.z + fa2.w*u2.w
             + fa3.x*u3.x + fa3.y*u3.y + fa3.z*u3.z + fa3.w*u3.w;
    float pB = fb0.x*u0.x + fb0.y*u0.y + fb0.z*u0.z + fb0.w*u0.w
             + fb1.x*u1.x + fb1.y*u1.y + fb1.z*u1.z + fb1.w*u1.w
             + fb2.x*u2.x + fb2.y*u2.y + fb2.z*u2.z + fb2.w*u2.w
             + fb3.x*u3.x + fb3.y*u3.y + fb3.z*u3.z + fb3.w*u3.w;

    #pragma unroll
    for (int off = 16; off; off >>= 1) {
        pA += __shfl_xor_sync(0xffffffffu, pA, off);
        pB += __shfl_xor_sync(0xffffffffu, pB, off);
    }

    // no-max exp weights (scores O(1); validated R10-R14)
    const float wA = __expf(pA * mtA.y);
    const float wB = __expf(pB * mtB.y);
    const float l  = wA + wB;

    // weighted ctx from registers (no second memory pass)
    float4 x0, x1, x2, x3;
    x0.x = wA*fa0.x + wB*fb0.x; x0.y = wA*fa0.y + wB*fb0.y;
    x0.z = wA*fa0.z + wB*fb0.z; x0.w = wA*fa0.w + wB*fb0.w;
    x1.x = wA*fa1.x + wB*fb1.x; x1.y = wA*fa1.y + wB*fb1.y;
    x1.z = wA*fa1.z + wB*fb1.z; x1.w = wA*fa1.w + wB*fb1.w;
    x2.x = wA*fa2.x + wB*fb2.x; x2.y = wA*fa2.y + wB*fb2.y;
    x2.z = wA*fa2.z + wB*fb2.z; x2.w = wA*fa2.w + wB*fb2.w;
    x3.x = wA*fa3.x + wB*fb3.x; x3.y = wA*fa3.y + wB*fb3.y;
    x3.z = wA*fa3.z + wB*fb3.z; x3.w = wA*fa3.w + wB*fb3.w;

    // ---- CTA combine: plain sums of 4 warp partials ----
    if (lane == 0) sl[wid] = l;
    sctx[wid * 128 + lane]      = x0;
    sctx[wid * 128 + 32 + lane] = x1;
    sctx[wid * 128 + 64 + lane] = x2;
    sctx[wid * 128 + 96 + lane] = x3;
    __syncthreads();

    const int idx = b * NPART + sp;
    {
        if (tid == 0)
            g_l[idx] = sl[0] + sl[1] + sl[2] + sl[3];
        const float4 a0 = sctx[tid], a1 = sctx[128 + tid];
        const float4 a2 = sctx[256 + tid], a3 = sctx[384 + tid];
        float4 comb;
        comb.x = (a0.x + a1.x) + (a2.x + a3.x);
        comb.y = (a0.y + a1.y) + (a2.y + a3.y);
        comb.z = (a0.z + a1.z) + (a2.z + a3.z);
        comb.w = (a0.w + a1.w) + (a2.w + a3.w);
        ((float4*)g_pctx)[(size_t)idx * (DM / 4) + tid] = comb;
    }

    // ---- fused finish: last CTA of batch b sums 32 partials + applies W_v ----
    __threadfence();
    __syncthreads();
    if (tid == 0) slast = atomicAdd(&g_cnt[b], 1u);
    __syncthreads();
    if (slast == NPART - 1) {
        float L = 0.f;
        #pragma unroll 8
        for (int i = 0; i < NPART; i++) L += g_l[b * NPART + i];
        const float invL = 1.0f / L;

        float4 a2 = make_float4(0.f, 0.f, 0.f, 0.f);
        const float4* pc = (const float4*)g_pctx + (size_t)b * NPART * (DM / 4) + tid;
        #pragma unroll 8
        for (int i = 0; i < NPART; i++) {
            const float4 v = pc[(size_t)i * (DM / 4)];
            a2.x += v.x; a2.y += v.y; a2.z += v.z; a2.w += v.w;
        }
        a2.x *= invL; a2.y *= invL; a2.z *= invL; a2.w *= invL;
        __syncthreads();
        sctx[tid] = a2;               // ctx_emb slice (128 float4)
        __syncthreads();

        // context[b, v] = sum_d ctx_emb[d] * Wv[v, d]   (thread v = tid)
        float s0a = 0.f, s1a = 0.f, s2a = 0.f, s3a = 0.f;
        const float4* wv = (const float4*)Wv + (size_t)tid * (DM / 4);
        #pragma unroll 8
        for (int d = 0; d < DM / 4; d += 4) {
            const float4 wa = wv[d],     ca = sctx[d];
            const float4 wb = wv[d + 1], cb = sctx[d + 1];
            const float4 wc = wv[d + 2], cc = sctx[d + 2];
            const float4 wd = wv[d + 3], cd = sctx[d + 3];
            s0a += wa.x*ca.x + wa.y*ca.y + wa.z*ca.z + wa.w*ca.w;
            s1a += wb.x*cb.x + wb.y*cb.y + wb.z*cb.z + wb.w*cb.w;
            s2a += wc.x*cc.x + wc.y*cc.y + wc.z*cc.z + wc.w*cc.w;
            s3a += wd.x*cd.x + wd.y*cd.y + wd.z*cd.z + wd.w*cd.w;
        }
        out[(size_t)b * DV + tid] = (s0a + s1a) + (s2a + s3a);
    }
}

// ============================================================================
extern "C" void kernel_launch(void* const* d_in, const int* in_sizes, int n_in,
                              void* d_out, int out_size)
{
    const float* query = (const float*)d_in[0];   // [64, 512]
    const float* embs  = (const float*)d_in[1];   // [64, 32, 256, 512]
    const float* Wq    = (const float*)d_in[2];   // [128, 512]
    const float* Wk    = (const float*)d_in[3];   // [128, 512]
    const float* Wv    = (const float*)d_in[4];   // [128, 512]
    const float* lags  = (const float*)d_in[5];   // [256]
    const float* gates = (const float*)d_in[6];   // [256]
    const void*  ml    = (n_in > 7) ? d_in[7] : nullptr;

    prep_kernel<<<dim3(4, NB), 256>>>(query, Wq, Wk, lags, gates, ml);
    main_kernel<<<dim3(CPB, NB), 128>>>(embs, Wv, (float*)d_out);
}